// round 2
// baseline (speedup 1.0000x reference)
#include <cuda_runtime.h>

// GwcVolumeCostProcessor: build [1, 64, 48, 128, 240] cost volume.
//   ch 0..39  : groupwise correlation, mean over 8 channels of ref_gwc * shift(tgt_gwc, d)
//   ch 40..51 : ref_concat * (w >= d)
//   ch 52..63 : shift(tgt_concat, d)   (zero for w < d)

#define HH 128
#define WW 240
#define DD 48
#define NG 40
#define CPG 8
#define HW (HH * WW)
#define W4 (WW / 4)  // 60

// ---------------- gwc kernel ----------------
// One block per (group g, row h). Load 8x240 ref + 8x240 tgt rows into smem,
// hold ref channel values in registers, sweep all 48 disparities.
__global__ __launch_bounds__(256) void gwc_kernel(
    const float* __restrict__ ref, const float* __restrict__ tgt,
    float* __restrict__ out)
{
    __shared__ float sref[CPG][WW];
    __shared__ float stgt[CPG][WW];

    const int g = blockIdx.x;
    const int h = blockIdx.y;
    const int tid = threadIdx.x;

    const float* refp = ref + ((size_t)g * CPG) * HW + (size_t)h * WW;
    const float* tgtp = tgt + ((size_t)g * CPG) * HW + (size_t)h * WW;

    // cooperative vectorized load: 8 channels x 60 float4 per array
    for (int i = tid; i < CPG * W4; i += 256) {
        int c = i / W4;
        int w4 = (i - c * W4) * 4;
        *(float4*)&sref[c][w4] = *(const float4*)(refp + (size_t)c * HW + w4);
        *(float4*)&stgt[c][w4] = *(const float4*)(tgtp + (size_t)c * HW + w4);
    }
    __syncthreads();

    const int w = tid;
    if (w >= WW) return;

    float r[CPG];
#pragma unroll
    for (int c = 0; c < CPG; c++) r[c] = sref[c][w];

    float* op = out + (((size_t)g * DD) * HH + h) * WW + w;

    const int dmax = (w + 1 < DD) ? (w + 1) : DD;
    int d = 0;
    for (; d < dmax; d++) {
        float acc = 0.0f;
#pragma unroll
        for (int c = 0; c < CPG; c++) acc += r[c] * stgt[c][w - d];
        *op = acc * 0.125f;
        op += HW;
    }
    for (; d < DD; d++) {  // w < d region is exactly zero
        *op = 0.0f;
        op += HW;
    }
}

// ---------------- concat kernel ----------------
// One block per (c_out in 0..23, d). Threads stream the 128x240 plane.
__global__ __launch_bounds__(256) void concat_kernel(
    const float* __restrict__ refc, const float* __restrict__ tgtc,
    float* __restrict__ out)
{
    const int cd = blockIdx.x;
    const int c = cd / DD;      // 0..23
    const int d = cd % DD;      // 0..47
    const int tid = threadIdx.x;

    float* op = out + (size_t)(NG + c) * DD * HW + (size_t)d * HW;

    if (c < 12) {
        const float* rp = refc + (size_t)c * HW;
        for (int i = tid; i < HH * W4; i += 256) {
            int h = i / W4;
            int w4 = (i - h * W4) * 4;
            float4 v = *(const float4*)(rp + (size_t)h * WW + w4);
            if (w4 < d) {  // only boundary blocks need masking
                if (w4 + 0 < d) v.x = 0.0f;
                if (w4 + 1 < d) v.y = 0.0f;
                if (w4 + 2 < d) v.z = 0.0f;
                if (w4 + 3 < d) v.w = 0.0f;
            }
            *(float4*)(op + (size_t)h * WW + w4) = v;
        }
    } else {
        const float* tp = tgtc + (size_t)(c - 12) * HW;
        for (int i = tid; i < HH * W4; i += 256) {
            int h = i / W4;
            int w4 = (i - h * W4) * 4;
            const float* row = tp + (size_t)h * WW;
            float4 v;
            v.x = (w4 + 0 >= d) ? row[w4 + 0 - d] : 0.0f;
            v.y = (w4 + 1 >= d) ? row[w4 + 1 - d] : 0.0f;
            v.z = (w4 + 2 >= d) ? row[w4 + 2 - d] : 0.0f;
            v.w = (w4 + 3 >= d) ? row[w4 + 3 - d] : 0.0f;
            *(float4*)(op + (size_t)h * WW + w4) = v;
        }
    }
}

extern "C" void kernel_launch(void* const* d_in, const int* in_sizes, int n_in,
                              void* d_out, int out_size)
{
    const float* ref_gwc    = (const float*)d_in[0];
    const float* tgt_gwc    = (const float*)d_in[1];
    const float* ref_concat = (const float*)d_in[2];
    const float* tgt_concat = (const float*)d_in[3];
    float* out = (float*)d_out;

    dim3 grid_gwc(NG, HH);  // 40 x 128 blocks
    gwc_kernel<<<grid_gwc, 256>>>(ref_gwc, tgt_gwc, out);

    concat_kernel<<<24 * DD, 256>>>(ref_concat, tgt_concat, out);
}

// round 3
// speedup vs baseline: 1.1884x; 1.1884x over previous
#include <cuda_runtime.h>

// Fused GwcVolumeCostProcessor: out [1, 64, 48, 128, 240] f32
//   ch 0..39  : groupwise correlation (mean over 8 ch of ref_gwc * shift(tgt_gwc,d))
//   ch 40..51 : ref_concat * (w >= d)
//   ch 52..63 : shift(tgt_concat, d)

#define HH 128
#define WW 240
#define DD 48
#define NG 40
#define CPG 8
#define HW (HH * WW)
#define W4 60                    // float4s per row
#define PAD 48                   // left zero-pad for tgt window
#define TW (PAD + WW)            // 288 padded row
#define GWC_BLOCKS (NG * HH)     // 5120
#define CAT_BLOCKS (24 * DD * 2) // 2304 : (c, d, h-half)

__global__ __launch_bounds__(64) void fused_kernel(
    const float* __restrict__ ref, const float* __restrict__ tgt,
    const float* __restrict__ refc, const float* __restrict__ tgtc,
    float* __restrict__ out)
{
    const int bid = blockIdx.x;
    const int tid = threadIdx.x;

    if (bid < GWC_BLOCKS) {
        // ---------------- gwc: one block per (group, h-row) ----------------
        __shared__ float stgt[CPG][TW];

        const int g = bid >> 7;     // bid / 128
        const int h = bid & 127;

        const float* tgtp = tgt + ((size_t)g * CPG) * HW + (size_t)h * WW;

        // Fill padded tgt rows: 8 channels x 72 float4 (first 12 float4 = zeros)
        for (int i = tid; i < CPG * (TW / 4); i += 64) {
            int c = i / (TW / 4);
            int x = i - c * (TW / 4);
            float4 v;
            if (x < PAD / 4) v = make_float4(0.f, 0.f, 0.f, 0.f);
            else v = *(const float4*)(tgtp + (size_t)c * HW + (size_t)(x - PAD / 4) * 4);
            *(float4*)&stgt[c][x * 4] = v;
        }
        __syncthreads();

        if (tid >= W4) return;
        const int w4 = tid * 4;

        // ref channel values -> registers (coalesced LDG.128, skip smem)
        const float* refp = ref + ((size_t)g * CPG) * HW + (size_t)h * WW + w4;
        float4 r[CPG];
#pragma unroll
        for (int c = 0; c < CPG; c++) r[c] = *(const float4*)(refp + (size_t)c * HW);

        // sliding window: win[c][k] = stgt_padded[c][PAD + w4 - d + k]
        float win[CPG][4];
#pragma unroll
        for (int c = 0; c < CPG; c++) {
            float4 v = *(const float4*)&stgt[c][PAD + w4];
            win[c][0] = v.x; win[c][1] = v.y; win[c][2] = v.z; win[c][3] = v.w;
        }

        float* op = out + (((size_t)g * DD) * HH + h) * WW + w4;
#pragma unroll 4
        for (int d = 0; d < DD; d++) {
            float4 acc = make_float4(0.f, 0.f, 0.f, 0.f);
#pragma unroll
            for (int c = 0; c < CPG; c++) {
                acc.x += r[c].x * win[c][0];
                acc.y += r[c].y * win[c][1];
                acc.z += r[c].z * win[c][2];
                acc.w += r[c].w * win[c][3];
            }
            acc.x *= 0.125f; acc.y *= 0.125f; acc.z *= 0.125f; acc.w *= 0.125f;
            *(float4*)op = acc;
            op += HW;

            // shift window for d+1 (unroll-4 turns these into register renames)
#pragma unroll
            for (int c = 0; c < CPG; c++) {
                win[c][3] = win[c][2];
                win[c][2] = win[c][1];
                win[c][1] = win[c][0];
                win[c][0] = stgt[c][PAD + w4 - (d + 1)];
            }
        }
    } else {
        // ---------------- concat: one block per (c, d, h-half) ----------------
        const int cb   = bid - GWC_BLOCKS;
        const int c    = cb / (DD * 2);
        const int rem  = cb - c * (DD * 2);
        const int d    = rem >> 1;
        const int half = rem & 1;

        float* op = out + (size_t)(NG + c) * DD * HW + (size_t)d * HW
                        + (size_t)half * 64 * WW;

        if (c < 12) {
            const float* rp = refc + (size_t)c * HW + (size_t)half * 64 * WW;
            for (int i = tid; i < 64 * W4; i += 64) {
                int h  = i / W4;
                int w4 = (i - h * W4) * 4;
                float4 v = *(const float4*)(rp + h * WW + w4);
                if (w4 < d) {
                    if (w4 + 0 < d) v.x = 0.f;
                    if (w4 + 1 < d) v.y = 0.f;
                    if (w4 + 2 < d) v.z = 0.f;
                    if (w4 + 3 < d) v.w = 0.f;
                }
                *(float4*)(op + h * WW + w4) = v;
            }
        } else {
            const float* tp = tgtc + (size_t)(c - 12) * HW + (size_t)half * 64 * WW;
            for (int i = tid; i < 64 * W4; i += 64) {
                int h  = i / W4;
                int w4 = (i - h * W4) * 4;
                const float* row = tp + h * WW;
                float4 v;
                v.x = (w4 + 0 >= d) ? row[w4 + 0 - d] : 0.f;
                v.y = (w4 + 1 >= d) ? row[w4 + 1 - d] : 0.f;
                v.z = (w4 + 2 >= d) ? row[w4 + 2 - d] : 0.f;
                v.w = (w4 + 3 >= d) ? row[w4 + 3 - d] : 0.f;
                *(float4*)(op + h * WW + w4) = v;
            }
        }
    }
}

extern "C" void kernel_launch(void* const* d_in, const int* in_sizes, int n_in,
                              void* d_out, int out_size)
{
    const float* ref_gwc    = (const float*)d_in[0];
    const float* tgt_gwc    = (const float*)d_in[1];
    const float* ref_concat = (const float*)d_in[2];
    const float* tgt_concat = (const float*)d_in[3];
    float* out = (float*)d_out;

    fused_kernel<<<GWC_BLOCKS + CAT_BLOCKS, 64>>>(
        ref_gwc, tgt_gwc, ref_concat, tgt_concat, out);
}